// round 17
// baseline (speedup 1.0000x reference)
#include <cuda_runtime.h>
#include <math.h>

// Problem constants
#define Bn   32
#define Nn   256
#define Hn   64
#define EPSf 1e-6f

// Table: KI intervals in d over [0, DMAX]; one float4 f-cubic each (power basis).
#define KI    256
#define DMAXf 20.0f

#define MAGICf 8388608.0f   // 2^23

// Device scratch (zero-init; finalizer restores zeros -> graph-replay safe)
__device__ float4   g_tab[KI];
__device__ float    g_v[Bn * Nn * 3];   // accumulated via atomics, re-zeroed
__device__ float    g_tr[Bn];           // batch trace sums, re-zeroed
__device__ unsigned g_ticket[Bn];

__device__ __forceinline__ float fast_tanh(float z)
{
    float az = fabsf(z);
    float e  = __expf(-2.f * az);
    float t  = __fdividef(1.f - e, 1.f + e);
    return copysignf(t, z);
}

// ---------------------------------------------------------------------------
// Kernel 1: table build (proven, unchanged). 32 blocks x 1024 threads.
// ---------------------------------------------------------------------------
__global__ void __launch_bounds__(1024)
table_kernel(const float* __restrict__ t_in,
             const float* __restrict__ W1,
             const float* __restrict__ b1,
             const float* __restrict__ W2,
             const float* __restrict__ b2,
             const float* __restrict__ W3,
             const float* __restrict__ b3)
{
    const int tid = threadIdx.x;
    const int blk = blockIdx.x;

    __shared__ float  sW2[Hn * Hn];
    __shared__ float2 sh1[9][Hn];
    __shared__ float2 s_node[10];
    __shared__ float  s_red[9][2][2];

    const float hstep = DMAXf / (float)KI;

    reinterpret_cast<float4*>(sW2)[tid] =
        reinterpret_cast<const float4*>(W2)[tid];

    const int slot = tid >> 6;
    const int p    = tid & 63;
    const int node = blk * 8 + slot;
    const float t  = t_in[0];
    const float d  = (float)node * hstep;

    if (slot < 9) {
        float w0 = W1[p];
        float z  = fmaf(d, w0, fmaf(t, W1[64 + p], b1[p]));
        float h1 = fast_tanh(z);
        float e1 = 1.f - h1 * h1;
        sh1[slot][p] = make_float2(h1, e1 * w0);
    }
    __syncthreads();

    float pf = 0.f, pfp = 0.f;
    if (slot < 9) {
        float s  = b2[p];
        float sd = 0.f;
#pragma unroll 8
        for (int l = 0; l < Hn; l++) {
            float  w2 = sW2[l * 64 + p];
            float2 hv = sh1[slot][l];
            s  = fmaf(w2, hv.x, s);
            sd = fmaf(w2, hv.y, sd);
        }
        float h2 = fast_tanh(s);
        float e2 = 1.f - h2 * h2;
        float w3 = W3[p];
        pf  = w3 * h2;
        pfp = w3 * e2 * sd;
    }

    const unsigned FULL = 0xffffffffu;
#pragma unroll
    for (int off = 16; off; off >>= 1) {
        pf  += __shfl_down_sync(FULL, pf,  off);
        pfp += __shfl_down_sync(FULL, pfp, off);
    }
    if (slot < 9 && (p & 31) == 0) {
        int ws = p >> 5;
        s_red[slot][ws][0] = pf;
        s_red[slot][ws][1] = pfp;
    }
    __syncthreads();
    if (slot < 9 && p == 0) {
        s_node[slot] = make_float2(
            s_red[slot][0][0] + s_red[slot][1][0] + b3[0],
            s_red[slot][0][1] + s_red[slot][1][1]);
    }
    __syncthreads();

    if (tid < 8) {
        float2 n0 = s_node[tid];
        float2 n1 = s_node[tid + 1];
        float P0 = n0.x, P1 = n1.x;
        float M0 = hstep * n0.y, M1 = hstep * n1.y;
        g_tab[blk * 8 + tid] = make_float4(
            P0, M0,
            3.f * (P1 - P0) - 2.f * M0 - M1,
            2.f * (P0 - P1) + M0 + M1);
    }
}

// ---------------------------------------------------------------------------
// Kernel 2: symmetric tiled pairs. 320 blocks x 512 threads.
// Block -> (batch b = blk/10, tile tt = blk%10).
//   tt 0..3  : diagonal tile (g, g)   — 64x64 maskless, row sums only
//   tt 4..9  : cross tile (ga, gb)    — 64x64 once; +r*f to rows, -r*f to
//              cols, trace term counted x2.
// Warp w owns rows 4w..4w+3; lanes sweep 64 cols in 2 chunks of 32.
// ---------------------------------------------------------------------------
__global__ void __launch_bounds__(512, 2)
pairs_kernel(const float* __restrict__ x, float* __restrict__ out)
{
    const int tid = threadIdx.x;
    const int blk = blockIdx.x;

    __shared__ float4   stab[KI];        // 4 KB
    __shared__ float4   sxsA[64];        // 1 KB (row group)
    __shared__ float4   sxsB[64];        // 1 KB (col group)
    __shared__ float    s_col[64][3];    // column partial sums
    __shared__ float    s_tred[16];      // per-warp trace partials
    __shared__ unsigned s_tk;
    __shared__ float    s_m[3];

    const float inv_step = (float)KI / DMAXf;
    const float UMAXf    = (float)KI - 0.001f;

    const int b  = blk / 10;
    const int tt = blk - b * 10;
    int ga, gb;
    bool cross;
    if (tt < 4)      { ga = tt; gb = tt; cross = false; }
    else {
        int e = tt - 4;   // (0,1)(0,2)(0,3)(1,2)(1,3)(2,3)
        ga = (e < 3) ? 0 : ((e < 5) ? 1 : 2);
        gb = (e < 3) ? e + 1 : ((e < 5) ? e - 1 : 3);   // FIXED (was e-2)
        cross = true;
    }

    // ---- stage positions (two 64-groups), table, zero s_col ----
    if (tid < 64) {
        const float* xa = x + (b * Nn + ga * 64 + tid) * 3;
        sxsA[tid] = make_float4(xa[0], xa[1], xa[2], 0.f);
    } else if (tid < 128) {
        int l = tid - 64;
        const float* xb = x + (b * Nn + gb * 64 + l) * 3;
        sxsB[l] = make_float4(xb[0], xb[1], xb[2], 0.f);
    }
    if (tid < KI) stab[tid] = g_tab[tid];
    if (tid < 192) reinterpret_cast<float*>(s_col)[tid] = 0.f;
    __syncthreads();

    const int w    = tid >> 5;           // 0..15
    const int lane = tid & 31;

    float rA[4][3];
#pragma unroll
    for (int q = 0; q < 4; q++) { rA[q][0] = 0.f; rA[q][1] = 0.f; rA[q][2] = 0.f; }
    float colv[2][3];
#pragma unroll
    for (int c = 0; c < 2; c++) { colv[c][0] = 0.f; colv[c][1] = 0.f; colv[c][2] = 0.f; }
    float tsum = 0.f;

#pragma unroll
    for (int c = 0; c < 2; c++) {
        const float4 XJ = sxsB[c * 32 + lane];
#pragma unroll
        for (int q = 0; q < 4; q++) {
            const float4 XI = sxsA[(w << 2) + q];       // warp broadcast
            float r0 = XI.x - XJ.x, r1 = XI.y - XJ.y, r2 = XI.z - XJ.z;
            float d2   = fmaf(r0, r0, fmaf(r1, r1, fmaf(r2, r2, EPSf)));
            float rinv = rsqrtf(d2);
            float du   = d2 * inv_step;
            float u    = fminf(du * rinv, UMAXf);
            float uf   = __fadd_rz(u, MAGICf);
            int   k    = __float_as_int(uf) & 0x7FFFFF;
            float wf   = u - (uf - MAGICf);
            float4 A   = stab[k];
            float qq   = fmaf(A.w, wf, A.z);
            float f    = fmaf(fmaf(qq, wf, A.y), wf, A.x);
            float fpw  = fmaf(fmaf(A.w, wf, qq + qq), wf, A.y);
            float v0 = r0 * f, v1 = r1 * f, v2 = r2 * f;
            rA[q][0] += v0; rA[q][1] += v1; rA[q][2] += v2;
            tsum += fmaf(fpw * inv_step * (d2 - EPSf), rinv, 3.f * f);
            if (cross) {
                colv[c][0] += v0; colv[c][1] += v1; colv[c][2] += v2;
            }
        }
    }

    // ---- row sums: shfl reduce, lane0 scatters to g_v ----
    const unsigned FULL = 0xffffffffu;
#pragma unroll
    for (int q = 0; q < 4; q++)
#pragma unroll
        for (int cc = 0; cc < 3; cc++) {
            float v = rA[q][cc];
#pragma unroll
            for (int off = 16; off; off >>= 1)
                v += __shfl_down_sync(FULL, v, off);
            rA[q][cc] = v;
        }
#pragma unroll
    for (int off = 16; off; off >>= 1)
        tsum += __shfl_down_sync(FULL, tsum, off);

    if (lane == 0) {
#pragma unroll
        for (int q = 0; q < 4; q++) {
            int row = b * Nn + ga * 64 + (w << 2) + q;
            atomicAdd(&g_v[row * 3 + 0], rA[q][0]);
            atomicAdd(&g_v[row * 3 + 1], rA[q][1]);
            atomicAdd(&g_v[row * 3 + 2], rA[q][2]);
        }
        s_tred[w] = tsum;
    }

    // ---- column partials into smem (cross tiles only) ----
    if (cross) {
#pragma unroll
        for (int c = 0; c < 2; c++) {
            int col = c * 32 + lane;
            atomicAdd(&s_col[col][0], colv[c][0]);
            atomicAdd(&s_col[col][1], colv[c][1]);
            atomicAdd(&s_col[col][2], colv[c][2]);
        }
    }
    __syncthreads();

    // ---- column scatter (negated) ----
    if (cross && tid < 192) {
        int col = tid / 3, cc = tid - col * 3;
        atomicAdd(&g_v[(b * Nn + gb * 64 + col) * 3 + cc], -s_col[col][cc]);
    }

    // ---- block trace total ----
    if (tid == 0) {
        float T = 0.f;
#pragma unroll
        for (int ww = 0; ww < 16; ww++) T += s_tred[ww];
        if (cross) {
            T *= 2.f;                       // symmetric trace term counts both ways
        } else {
            // subtract 64 self terms: 3*f(u_self) each (bitwise-identical eval)
            float rinvs = rsqrtf(EPSf);
            float us  = fminf((EPSf * inv_step) * rinvs, UMAXf);
            float ufs = __fadd_rz(us, MAGICf);
            int   ks  = __float_as_int(ufs) & 0x7FFFFF;
            float wfs = us - (ufs - MAGICf);
            float4 As = stab[ks];
            float qs  = fmaf(As.w, wfs, As.z);
            float fs  = fmaf(fmaf(qs, wfs, As.y), wfs, As.x);
            T -= 192.f * fs;                // 64 rows x 3*f_self
        }
        atomicAdd(&g_tr[b], T);
    }
    __syncthreads();

    // ===== per-batch ticket: 10th arriver finalizes this batch =====
    if (tid == 0) {
        __threadfence();
        s_tk = atomicAdd(&g_ticket[b], 1u);
        if (s_tk == 9) __threadfence();
    }
    __syncthreads();

    if (s_tk == 9) {
        if (tid < 3) s_m[tid] = 0.f;
        __syncthreads();

        // each thread owns elements tid and tid+512 of this batch's 768
        float val0 = g_v[b * (Nn * 3) + tid];
        int   idx1 = tid + 512;
        float val1 = (idx1 < Nn * 3) ? g_v[b * (Nn * 3) + idx1] : 0.f;
        atomicAdd(&s_m[tid % 3], val0);
        if (idx1 < Nn * 3) atomicAdd(&s_m[idx1 % 3], val1);
        __syncthreads();

        const float invNm1 = 1.f / (float)(Nn - 1);
        const float invN   = 1.f / (float)Nn;

        out[b * (Nn * 3) + tid] = (val0 - s_m[tid % 3] * invN) * invNm1;
        g_v[b * (Nn * 3) + tid] = 0.f;
        if (idx1 < Nn * 3) {
            out[b * (Nn * 3) + idx1] = (val1 - s_m[idx1 % 3] * invN) * invNm1;
            g_v[b * (Nn * 3) + idx1] = 0.f;
        }
        if (tid == 0) {
            out[Bn * Nn * 3 + b] = g_tr[b] * invNm1 * (1.f - invN);
            g_tr[b]     = 0.f;
            g_ticket[b] = 0u;
        }
    }
}

// ---------------------------------------------------------------------------
extern "C" void kernel_launch(void* const* d_in, const int* in_sizes, int n_in,
                              void* d_out, int out_size)
{
    const float* t  = (const float*)d_in[0];
    const float* x  = (const float*)d_in[1];
    const float* W1 = (const float*)d_in[2];
    const float* b1 = (const float*)d_in[3];
    const float* W2 = (const float*)d_in[4];
    const float* b2 = (const float*)d_in[5];
    const float* W3 = (const float*)d_in[6];
    const float* b3 = (const float*)d_in[7];

    table_kernel<<<32, 1024>>>(t, W1, b1, W2, b2, W3, b3);
    pairs_kernel<<<320, 512>>>(x, (float*)d_out);
}